// round 7
// baseline (speedup 1.0000x reference)
#include <cuda_runtime.h>
#include <cstdint>

#define NB 64
#define NL 64
#define NC 16
#define DM 450          // EMB(300) + 3*50
#define NTOK 8192       // 2 * B * L

typedef unsigned long long ull;

__device__ __forceinline__ void upk2(ull v, float& lo, float& hi) {
    asm("mov.b64 {%0, %1}, %2;" : "=f"(lo), "=f"(hi) : "l"(v));
}
__device__ __forceinline__ void fma2(ull& d, ull a, ull b) {
    asm("fma.rn.f32x2 %0, %1, %2, %0;" : "+l"(d) : "l"(a), "l"(b));
}

__device__ float g_x[(size_t)NTOK * DM];
__device__ float g_y[(size_t)NTOK * DM];
__device__ float g_M[60000];
__device__ float g_s1[NTOK];
__device__ float g_s2[NTOK];

// ---------------------------------------------------------------------------
// 1) Precompute char tables: M[k][v][f] = sum_ch cemb[v][ch] * w[f][ch][k]
// ---------------------------------------------------------------------------
__global__ void precomp_kernel(const float* __restrict__ cemb,
                               const float* __restrict__ w3,
                               const float* __restrict__ w4,
                               const float* __restrict__ w5) {
    int idx = blockIdx.x * blockDim.x + threadIdx.x;
    if (idx >= 60000) return;
    const float* W;
    int WD, local;
    if (idx < 15000)      { W = w3; WD = 3; local = idx; }
    else if (idx < 35000) { W = w4; WD = 4; local = idx - 15000; }
    else                  { W = w5; WD = 5; local = idx - 35000; }
    int f  = local % 50;
    int kv = local / 50;
    int v  = kv % 100;
    int k  = kv / 100;
    const float* e  = cemb + v * 64;
    const float* wp = W + (size_t)f * 64 * WD + k;
    float s = 0.f;
#pragma unroll 8
    for (int ch = 0; ch < 64; ch++) s += e[ch] * wp[ch * WD];
    g_M[idx] = s;
}

// ---------------------------------------------------------------------------
// 2) Embedding + char features -> g_x[tok][450]
// ---------------------------------------------------------------------------
__global__ void embed_kernel(const int* __restrict__ q1, const int* __restrict__ q2,
                             const int* __restrict__ q1c, const int* __restrict__ q2c,
                             const float* __restrict__ wemb,
                             const float* __restrict__ b3, const float* __restrict__ b4,
                             const float* __restrict__ b5) {
    int tok = blockIdx.x;
    int r   = tok >> 12;
    int li  = tok & 4095;
    const int* q  = r ? q2 : q1;
    const int* qc = r ? q2c : q1c;
    int tid = threadIdx.x;

    __shared__ int ids[16];
    if (tid < 16) ids[tid] = qc[li * 16 + tid];
    __syncthreads();

    float* xrow = g_x + (size_t)tok * DM;
    const float* we = wemb + (size_t)q[li] * 300;
    for (int i = tid; i < 300; i += blockDim.x) xrow[i] = we[i];

    int f = tid;
    if (f < 150) {
        int fi, base, wd;
        float bias;
        if (f < 50)       { wd = 3; fi = f;       base = 0;     bias = b3[fi]; }
        else if (f < 100) { wd = 4; fi = f - 50;  base = 15000; bias = b4[fi]; }
        else              { wd = 5; fi = f - 100; base = 35000; bias = b5[fi]; }
        float m = 0.f;
        int tout = 16 - wd + 1;
        for (int t = 0; t < tout; t++) {
            float h = bias;
            for (int k = 0; k < wd; k++)
                h += g_M[base + (k * 100 + ids[t + k]) * 50 + fi];
            m = fmaxf(m, h);
        }
        xrow[300 + f] = m;
    }
}

// ---------------------------------------------------------------------------
// 3) Highway: y = x @ W^T + b ; out = sig(y)*relu(y) + (1-sig(y))*x
//    K-pair f32x2, 64x64 tile, thread tile 4x4 (32 acc regs) =>
//    <=64 regs total => 4 CTA/SM, 32 warps. Conflict-free LDS.128 both sides.
// ---------------------------------------------------------------------------
#define HBM 64
#define HBN 64
#define HBK 32
#define HKS 36   // row stride (32 k + 4 pad), 16B-aligned rows

__global__ __launch_bounds__(256, 4) void highway_kernel(int dir,
        const float* __restrict__ W, const float* __restrict__ bias) {
    const float* X = dir ? g_y : g_x;
    float* OUT     = dir ? g_x : g_y;
    __shared__ float As[HBM][HKS];
    __shared__ float Bs[HBN][HKS];
    int bm = blockIdx.y * HBM;
    int bn = blockIdx.x * HBN;
    int tid = threadIdx.x;
    int tm = (tid >> 4) * 4;   // 4 rows, broadcast across lanes 0-15
    int tc = tid & 15;         // cols tc + 16p, p=0..3
    // acc[i][p]: row tm+i, col tc+16p; pair = (even-k, odd-k) partials
    ull acc[4][4] = {};

    for (int k0 = 0; k0 < DM; k0 += HBK) {
        // A tile fill: 64 rows x 16 float2 (k-contiguous) -> 4 per thread
        for (int idx = tid; idx < HBM * 16; idx += 256) {
            int m = idx >> 4, c = idx & 15;
            int kk = k0 + 2 * c;
            float2 v = make_float2(0.f, 0.f);
            if (kk < DM) v = *(const float2*)&X[(size_t)(bm + m) * DM + kk];
            *(float2*)&As[m][2 * c] = v;
        }
        // B tile fill: 64 rows x 16 float2
        for (int idx = tid; idx < HBN * 16; idx += 256) {
            int n = idx >> 4, c = idx & 15;
            int kk = k0 + 2 * c;
            int gn = bn + n;
            float2 v = make_float2(0.f, 0.f);
            if (gn < DM && kk < DM) v = *(const float2*)&W[(size_t)gn * DM + kk];
            *(float2*)&Bs[n][2 * c] = v;
        }
        __syncthreads();
#pragma unroll
        for (int kq = 0; kq < HBK / 4; kq++) {
            ulonglong2 b0 = *(const ulonglong2*)&Bs[tc][4 * kq];
            ulonglong2 b1 = *(const ulonglong2*)&Bs[tc + 16][4 * kq];
            ulonglong2 b2 = *(const ulonglong2*)&Bs[tc + 32][4 * kq];
            ulonglong2 b3 = *(const ulonglong2*)&Bs[tc + 48][4 * kq];
#pragma unroll
            for (int i = 0; i < 4; i++) {
                ulonglong2 a = *(const ulonglong2*)&As[tm + i][4 * kq];
                fma2(acc[i][0], a.x, b0.x); fma2(acc[i][0], a.y, b0.y);
                fma2(acc[i][1], a.x, b1.x); fma2(acc[i][1], a.y, b1.y);
                fma2(acc[i][2], a.x, b2.x); fma2(acc[i][2], a.y, b2.y);
                fma2(acc[i][3], a.x, b3.x); fma2(acc[i][3], a.y, b3.y);
            }
        }
        __syncthreads();
    }

#pragma unroll
    for (int i = 0; i < 4; i++) {
        int m = bm + tm + i;
#pragma unroll
        for (int p = 0; p < 4; p++) {
            int n = bn + tc + 16 * p;
            if (n < DM) {
                float lo, hi;
                upk2(acc[i][p], lo, hi);
                float yy = lo + hi + bias[n];
                float g  = 1.f / (1.f + __expf(-yy));
                float xv = X[(size_t)m * DM + n];
                OUT[(size_t)m * DM + n] = g * fmaxf(yy, 0.f) + (1.f - g) * xv;
            }
        }
    }
}

// ---------------------------------------------------------------------------
// 4a) s1/s2 dots for one attn iteration: s1 = x.w1, s2 = x.w2, all 64 rows.
// ---------------------------------------------------------------------------
__global__ __launch_bounds__(256) void sdots_kernel(
        const float* __restrict__ Xin_base, const float* __restrict__ attw, int it) {
    int batch = blockIdx.x;
    const float* X  = Xin_base + (size_t)batch * 64 * DM;
    const float* aw = attw + it * (3 * DM);
    int tid = threadIdx.x;
    int warp = tid >> 5, lane = tid & 31;

    for (int dot = warp; dot < 128; dot += 8) {
        int row = dot & 63;
        const float* wv = (dot < 64) ? (aw + DM) : aw;
        const float* xv = X + row * DM;
        float a = 0.f;
        for (int d = lane * 2; d < DM; d += 64) {
            float2 x2 = *(const float2*)&xv[d];
            float2 w2 = *(const float2*)&wv[d];
            a += x2.x * w2.x + x2.y * w2.y;
        }
#pragma unroll
        for (int off = 16; off > 0; off >>= 1)
            a += __shfl_down_sync(0xffffffffu, a, off);
        if (lane == 0) {
            if (dot < 64) g_s2[batch * 64 + row] = a;
            else          g_s1[batch * 64 + row] = a;
        }
    }
}

// ---------------------------------------------------------------------------
// 4b) Self-attention: grid (2, 128), block = (batch, 32-row group), 256 thr.
// ---------------------------------------------------------------------------
__global__ __launch_bounds__(256) void attn_kernel(
        const int* __restrict__ q1_len, const int* __restrict__ q2_len,
        const float* __restrict__ attw, const float* __restrict__ attb,
        int it, int residual,
        const float* __restrict__ Xin_base, float* __restrict__ Xout_base) {
    int batch = blockIdx.y;
    int row0  = blockIdx.x * 32;
    int r = batch >> 6, b = batch & 63;
    int len = (r ? q2_len : q1_len)[b];
    const float* aw = attw + it * (3 * DM);
    float ab = attb[it];
    const float* X = Xin_base + (size_t)batch * 64 * DM;
    float* OUT     = Xout_base + (size_t)batch * 64 * DM;

    __shared__ float xw[64][68];
    __shared__ float xsD[64][68];
    __shared__ float s1s[32], s2s[64];

    int tid  = threadIdx.x;
    int warp = tid >> 5, lane = tid & 31;
    int tj2  = lane * 2;

    if (tid < 64)      s2s[tid] = g_s2[batch * 64 + tid];
    else if (tid < 96) s1s[tid - 64] = g_s1[batch * 64 + row0 + (tid - 64)] + ab;

    ull acc[4] = {0, 0, 0, 0};

    for (int d0 = 0; d0 < DM; d0 += 64) {
        int dn = DM - d0; if (dn > 64) dn = 64;
        __syncthreads();
        for (int idx = tid; idx < 64 * 64; idx += 256) {
            int j = idx >> 6, d = idx & 63;
            float v = 0.f;
            if (d < dn) v = X[j * DM + d0 + d] * aw[2 * DM + d0 + d];
            xw[d][j] = v;
        }
        for (int idx = tid; idx < 32 * 64; idx += 256) {
            int rr = idx >> 6, d = idx & 63;
            float v = (d < dn) ? X[(row0 + rr) * DM + d0 + d] : 0.f;
            *(float2*)&xsD[d][2 * rr] = make_float2(v, v);
        }
        __syncthreads();
#pragma unroll 4
        for (int d = 0; d < 64; d++) {
            ulonglong2 aA = *(const ulonglong2*)&xsD[d][8 * warp];
            ulonglong2 aB = *(const ulonglong2*)&xsD[d][8 * warp + 4];
            ull bw = *(const ull*)&xw[d][tj2];
            fma2(acc[0], aA.x, bw);
            fma2(acc[1], aA.y, bw);
            fma2(acc[2], aB.x, bw);
            fma2(acc[3], aB.y, bw);
        }
    }
    __syncthreads();

    {
        float2 s2p = *(const float2*)&s2s[tj2];
#pragma unroll
        for (int i = 0; i < 4; i++) {
            int lr = 4 * warp + i;
            float base = s1s[lr];
            float v0, v1;
            upk2(acc[i], v0, v1);
            v0 += base + s2p.x;
            v1 += base + s2p.y;
            float l0 = (tj2     < len) ? v0 : -1e-9f;
            float l1 = (tj2 + 1 < len) ? v1 : -1e-9f;
            float mx = fmaxf(l0, l1);
#pragma unroll
            for (int off = 16; off > 0; off >>= 1)
                mx = fmaxf(mx, __shfl_xor_sync(0xffffffffu, mx, off));
            float e0 = __expf(l0 - mx), e1 = __expf(l1 - mx);
            float s = e0 + e1;
#pragma unroll
            for (int off = 16; off > 0; off >>= 1)
                s += __shfl_xor_sync(0xffffffffu, s, off);
            float inv = 1.f / s;
            *(float2*)&xsD[tj2][2 * lr]     = make_float2(e0 * inv, e0 * inv);
            *(float2*)&xsD[tj2 + 1][2 * lr] = make_float2(e1 * inv, e1 * inv);
        }
    }

    float* xs = &xw[0][0];
    for (int d0 = 0; d0 < DM; d0 += 64) {
        int dn = DM - d0; if (dn > 64) dn = 64;
        __syncthreads();
        for (int idx = tid; idx < 64 * 32; idx += 256) {
            int j = idx >> 5, dp = idx & 31;
            float2 v = make_float2(0.f, 0.f);
            if (2 * dp < dn) v = *(const float2*)&X[j * DM + d0 + 2 * dp];
            *(float2*)&xs[j * 68 + 2 * dp] = v;
        }
        __syncthreads();
        ull o[4] = {0, 0, 0, 0};
#pragma unroll 4
        for (int j = 0; j < 64; j++) {
            ulonglong2 pA = *(const ulonglong2*)&xsD[j][8 * warp];
            ulonglong2 pB = *(const ulonglong2*)&xsD[j][8 * warp + 4];
            ull xv = *(const ull*)&xs[j * 68 + tj2];
            fma2(o[0], pA.x, xv);
            fma2(o[1], pA.y, xv);
            fma2(o[2], pB.x, xv);
            fma2(o[3], pB.y, xv);
        }
        int d = d0 + tj2;
#pragma unroll
        for (int i = 0; i < 4; i++) {
            int grow = row0 + 4 * warp + i;
            float a0, a1;
            upk2(o[i], a0, a1);
            if (residual) {
                float2 xv = *(const float2*)&xs[grow * 68 + tj2];
                a0 += xv.x;
                a1 += xv.y;
            }
            if (d < DM)     OUT[grow * DM + d]     = a0;
            if (d + 1 < DM) OUT[grow * DM + d + 1] = a1;
        }
    }
}

// ---------------------------------------------------------------------------
extern "C" void kernel_launch(void* const* d_in, const int* in_sizes, int n_in,
                              void* d_out, int out_size) {
    const int*   q1     = (const int*)d_in[0];
    const int*   q2     = (const int*)d_in[1];
    const int*   q1_len = (const int*)d_in[2];
    const int*   q2_len = (const int*)d_in[3];
    const int*   q1c    = (const int*)d_in[4];
    const int*   q2c    = (const int*)d_in[5];
    const float* wemb   = (const float*)d_in[6];
    const float* cemb   = (const float*)d_in[7];
    const float* cw3    = (const float*)d_in[8];
    const float* cb3    = (const float*)d_in[9];
    const float* cw4    = (const float*)d_in[10];
    const float* cb4    = (const float*)d_in[11];
    const float* cw5    = (const float*)d_in[12];
    const float* cb5    = (const float*)d_in[13];
    const float* hw_w   = (const float*)d_in[14];
    const float* hw_b   = (const float*)d_in[15];
    const float* attw   = (const float*)d_in[16];
    const float* attb   = (const float*)d_in[17];
    float* out = (float*)d_out;

    float* gx;
    float* gy;
    cudaGetSymbolAddress((void**)&gx, g_x);
    cudaGetSymbolAddress((void**)&gy, g_y);

    precomp_kernel<<<(60000 + 255) / 256, 256>>>(cemb, cw3, cw4, cw5);
    embed_kernel<<<NTOK, 160>>>(q1, q2, q1c, q2c, wemb, cb3, cb4, cb5);
    highway_kernel<<<dim3(8, 128), 256>>>(0, hw_w, hw_b);   // g_x -> g_y
    highway_kernel<<<dim3(8, 128), 256>>>(1, hw_w, hw_b);   // g_y -> g_x
    sdots_kernel<<<128, 256>>>(gx, attw, 0);
    attn_kernel<<<dim3(2, 128), 256>>>(q1_len, q2_len, attw, attb, 0, 1, gx, gy);
    sdots_kernel<<<128, 256>>>(gy, attw, 1);
    attn_kernel<<<dim3(2, 128), 256>>>(q1_len, q2_len, attw, attb, 1, 0, gy, out);
}

// round 10
// speedup vs baseline: 1.0429x; 1.0429x over previous
#include <cuda_runtime.h>
#include <cstdint>

#define NB 64
#define NL 64
#define NC 16
#define DM 450          // EMB(300) + 3*50
#define NTOK 8192       // 2 * B * L

typedef unsigned long long ull;

__device__ __forceinline__ ull pk2(float lo, float hi) {
    ull r; asm("mov.b64 %0, {%1, %2};" : "=l"(r) : "f"(lo), "f"(hi)); return r;
}
__device__ __forceinline__ void upk2(ull v, float& lo, float& hi) {
    asm("mov.b64 {%0, %1}, %2;" : "=f"(lo), "=f"(hi) : "l"(v));
}
__device__ __forceinline__ void fma2(ull& d, ull a, ull b) {
    asm("fma.rn.f32x2 %0, %1, %2, %0;" : "+l"(d) : "l"(a), "l"(b));
}

__device__ float g_x[(size_t)NTOK * DM];
__device__ float g_y[(size_t)NTOK * DM];
__device__ float g_M[60000];

// ---------------------------------------------------------------------------
// 1) Precompute char tables: M[k][v][f] = sum_ch cemb[v][ch] * w[f][ch][k]
// ---------------------------------------------------------------------------
__global__ void precomp_kernel(const float* __restrict__ cemb,
                               const float* __restrict__ w3,
                               const float* __restrict__ w4,
                               const float* __restrict__ w5) {
    int idx = blockIdx.x * blockDim.x + threadIdx.x;
    if (idx >= 60000) return;
    const float* W;
    int WD, local;
    if (idx < 15000)      { W = w3; WD = 3; local = idx; }
    else if (idx < 35000) { W = w4; WD = 4; local = idx - 15000; }
    else                  { W = w5; WD = 5; local = idx - 35000; }
    int f  = local % 50;
    int kv = local / 50;
    int v  = kv % 100;
    int k  = kv / 100;
    const float* e  = cemb + v * 64;
    const float* wp = W + (size_t)f * 64 * WD + k;
    float s = 0.f;
#pragma unroll 8
    for (int ch = 0; ch < 64; ch++) s += e[ch] * wp[ch * WD];
    g_M[idx] = s;
}

// ---------------------------------------------------------------------------
// 2) Embedding + char features -> g_x[tok][450]
// ---------------------------------------------------------------------------
__global__ void embed_kernel(const int* __restrict__ q1, const int* __restrict__ q2,
                             const int* __restrict__ q1c, const int* __restrict__ q2c,
                             const float* __restrict__ wemb,
                             const float* __restrict__ b3, const float* __restrict__ b4,
                             const float* __restrict__ b5) {
    int tok = blockIdx.x;
    int r   = tok >> 12;
    int li  = tok & 4095;
    const int* q  = r ? q2 : q1;
    const int* qc = r ? q2c : q1c;
    int tid = threadIdx.x;

    __shared__ int ids[16];
    if (tid < 16) ids[tid] = qc[li * 16 + tid];
    __syncthreads();

    float* xrow = g_x + (size_t)tok * DM;
    const float* we = wemb + (size_t)q[li] * 300;
    for (int i = tid; i < 300; i += blockDim.x) xrow[i] = we[i];

    int f = tid;
    if (f < 150) {
        int fi, base, wd;
        float bias;
        if (f < 50)       { wd = 3; fi = f;       base = 0;     bias = b3[fi]; }
        else if (f < 100) { wd = 4; fi = f - 50;  base = 15000; bias = b4[fi]; }
        else              { wd = 5; fi = f - 100; base = 35000; bias = b5[fi]; }
        float m = 0.f;
        int tout = 16 - wd + 1;
        for (int t = 0; t < tout; t++) {
            float h = bias;
            for (int k = 0; k < wd; k++)
                h += g_M[base + (k * 100 + ids[t + k]) * 50 + fi];
            m = fmaxf(m, h);
        }
        xrow[300 + f] = m;
    }
}

// ---------------------------------------------------------------------------
// 3) Highway: y = x @ W^T + b ; out = sig(y)*relu(y) + (1-sig(y))*x
//    K-pair f32x2, 128x64 tile, 512 threads, 4x4 thread tile (32 acc regs)
//    => <=64 regs => 2 CTA/SM = 32 warps. Conflict-free LDS.128 both sides.
// ---------------------------------------------------------------------------
#define HBM 128
#define HBN 64
#define HBK 32
#define HKS 36   // row stride (32 k + 4 pad), 16B-aligned rows

__global__ __launch_bounds__(512, 2) void highway_kernel(int dir,
        const float* __restrict__ W, const float* __restrict__ bias) {
    const float* X = dir ? g_y : g_x;
    float* OUT     = dir ? g_x : g_y;
    __shared__ float As[HBM][HKS];
    __shared__ float Bs[HBN][HKS];
    int bm = blockIdx.y * HBM;
    int bn = blockIdx.x * HBN;
    int tid = threadIdx.x;
    int tm = (tid >> 4) * 4;   // 32 row-groups x 4 rows = 128 rows
    int tc = tid & 15;         // cols tc + 16p, p=0..3
    // acc[i][p]: row tm+i, col tc+16p; pair = (even-k, odd-k) partials
    ull acc[4][4] = {};

    for (int k0 = 0; k0 < DM; k0 += HBK) {
        // A tile fill: 128 rows x 16 float2 (k-contiguous), 4 per thread
        for (int idx = tid; idx < HBM * 16; idx += 512) {
            int m = idx >> 4, c = idx & 15;
            int kk = k0 + 2 * c;
            float2 v = make_float2(0.f, 0.f);
            if (kk < DM) v = *(const float2*)&X[(size_t)(bm + m) * DM + kk];
            *(float2*)&As[m][2 * c] = v;
        }
        // B tile fill: 64 rows x 16 float2, 2 per thread
        for (int idx = tid; idx < HBN * 16; idx += 512) {
            int n = idx >> 4, c = idx & 15;
            int kk = k0 + 2 * c;
            int gn = bn + n;
            float2 v = make_float2(0.f, 0.f);
            if (gn < DM && kk < DM) v = *(const float2*)&W[(size_t)gn * DM + kk];
            *(float2*)&Bs[n][2 * c] = v;
        }
        __syncthreads();
#pragma unroll
        for (int kq = 0; kq < HBK / 4; kq++) {
            ulonglong2 b0 = *(const ulonglong2*)&Bs[tc][4 * kq];
            ulonglong2 b1 = *(const ulonglong2*)&Bs[tc + 16][4 * kq];
            ulonglong2 b2 = *(const ulonglong2*)&Bs[tc + 32][4 * kq];
            ulonglong2 b3 = *(const ulonglong2*)&Bs[tc + 48][4 * kq];
#pragma unroll
            for (int i = 0; i < 4; i++) {
                ulonglong2 a = *(const ulonglong2*)&As[tm + i][4 * kq];
                fma2(acc[i][0], a.x, b0.x); fma2(acc[i][0], a.y, b0.y);
                fma2(acc[i][1], a.x, b1.x); fma2(acc[i][1], a.y, b1.y);
                fma2(acc[i][2], a.x, b2.x); fma2(acc[i][2], a.y, b2.y);
                fma2(acc[i][3], a.x, b3.x); fma2(acc[i][3], a.y, b3.y);
            }
        }
        __syncthreads();
    }

#pragma unroll
    for (int i = 0; i < 4; i++) {
        int m = bm + tm + i;
#pragma unroll
        for (int p = 0; p < 4; p++) {
            int n = bn + tc + 16 * p;
            if (n < DM) {
                float lo, hi;
                upk2(acc[i][p], lo, hi);
                float yy = lo + hi + bias[n];
                float g  = 1.f / (1.f + __expf(-yy));
                float xv = X[(size_t)m * DM + n];
                OUT[(size_t)m * DM + n] = g * fmaxf(yy, 0.f) + (1.f - g) * xv;
            }
        }
    }
}

// ---------------------------------------------------------------------------
// 4) Self-attention (round-2 proven version). One block (512 thr) per batch.
//    scores[i][j] = s1[i] + s2[j] + sum_d x[i,d]*w3[d]*x[j,d] + b
//    soft mask (-1e-9 on j>=len, still in softmax) like the reference.
//    Softmax in-warp: warp w owns rows 4w..4w+3 across all 64 cols.
//    In-place update is safe: exactly one block touches each batch.
// ---------------------------------------------------------------------------
__global__ __launch_bounds__(512) void attn_kernel(
        const int* __restrict__ q1_len, const int* __restrict__ q2_len,
        const float* __restrict__ attw, const float* __restrict__ attb,
        int it, int last, float* __restrict__ dout) {
    int batch = blockIdx.x;
    int r = batch >> 6, b = batch & 63;
    int len = (r ? q2_len : q1_len)[b];
    const float* aw = attw + it * (3 * DM);
    float ab = attb[it];
    float* X = g_x + (size_t)batch * 64 * DM;

    __shared__ float xsT[64][68];   // phase A: [d][row]; phase C reused row-major [row][d]
    __shared__ float xw[64][68];    // phase A: w3-scaled [d][row]; later probs^T [j][row]
    __shared__ float s1[64], s2[64];

    int tid  = threadIdx.x;
    int warp = tid >> 5, lane = tid & 31;
    int ti  = warp * 4;       // this warp's 4 rows
    int tj2 = lane * 2;       // this thread's 2 cols

    if (tid < 64) { s1[tid] = 0.f; s2[tid] = 0.f; }

    ull acc[4] = {0, 0, 0, 0};   // acc[i]: row ti+i, cols (tj2, tj2+1)

    // ---- Phase A: scores + s1/s2 over d-tiles ----
    for (int d0 = 0; d0 < DM; d0 += 64) {
        int dn = min(64, DM - d0);
        __syncthreads();
        for (int idx = tid; idx < 64 * 64; idx += 512) {
            int row = idx >> 6, d = idx & 63;
            float v  = (d < dn) ? X[row * DM + d0 + d] : 0.f;
            float wv = (d < dn) ? aw[2 * DM + d0 + d] : 0.f;
            xsT[d][row] = v;
            xw[d][row]  = v * wv;
        }
        __syncthreads();

        // s1/s2 partial dots: warp owns rows ti..ti+3
#pragma unroll
        for (int rr = 0; rr < 4; rr++) {
            int row = ti + rr;
            float a1 = 0.f, a2 = 0.f;
            for (int d = lane; d < dn; d += 32) {
                float xv = xsT[d][row];
                a1 += xv * aw[d0 + d];
                a2 += xv * aw[DM + d0 + d];
            }
#pragma unroll
            for (int off = 16; off > 0; off >>= 1) {
                a1 += __shfl_down_sync(0xffffffffu, a1, off);
                a2 += __shfl_down_sync(0xffffffffu, a2, off);
            }
            if (lane == 0) { s1[row] += a1; s2[row] += a2; }
        }

        // (x*w3) @ x^T partial: broadcast LDS.128 (rows) + LDS.64 (col pair)
#pragma unroll 4
        for (int d = 0; d < 64; d++) {
            float4 a4 = *(const float4*)&xsT[d][ti];
            ull bw = *(const ull*)&xw[d][tj2];
            fma2(acc[0], pk2(a4.x, a4.x), bw);
            fma2(acc[1], pk2(a4.y, a4.y), bw);
            fma2(acc[2], pk2(a4.z, a4.z), bw);
            fma2(acc[3], pk2(a4.w, a4.w), bw);
        }
    }
    __syncthreads();   // s1/s2 complete; xw reads done

    // ---- Phase B: softmax, in-warp (warp has rows ti..ti+3, all cols) ----
    {
        float2 s2p = *(const float2*)&s2[tj2];
#pragma unroll
        for (int i = 0; i < 4; i++) {
            int row = ti + i;
            float base = s1[row] + ab;
            float v0, v1;
            upk2(acc[i], v0, v1);
            v0 += base + s2p.x;
            v1 += base + s2p.y;
            float l0 = (tj2     < len) ? v0 : -1e-9f;
            float l1 = (tj2 + 1 < len) ? v1 : -1e-9f;
            float mx = fmaxf(l0, l1);
#pragma unroll
            for (int off = 16; off > 0; off >>= 1)
                mx = fmaxf(mx, __shfl_xor_sync(0xffffffffu, mx, off));
            float e0 = __expf(l0 - mx), e1 = __expf(l1 - mx);
            float s = e0 + e1;
#pragma unroll
            for (int off = 16; off > 0; off >>= 1)
                s += __shfl_xor_sync(0xffffffffu, s, off);
            float inv = 1.f / s;
            xw[tj2][row]     = e0 * inv;   // probs transposed: xw[j][row]
            xw[tj2 + 1][row] = e1 * inv;
        }
    }
    __syncthreads();

    // ---- Phase C: att = P @ x; out / residual. xsT reused row-major. ----
    float* xs = &xsT[0][0];  // xs[row*68 + d]
    for (int d0 = 0; d0 < DM; d0 += 64) {
        int dn = min(64, DM - d0);
        for (int idx = tid; idx < 64 * 32; idx += 512) {
            int row = idx >> 5, dp = idx & 31;
            float2 v = make_float2(0.f, 0.f);
            if (2 * dp < dn) v = *(const float2*)&X[row * DM + d0 + 2 * dp];
            *(float2*)&xs[row * 68 + 2 * dp] = v;
        }
        __syncthreads();
        ull acco[4] = {0, 0, 0, 0};   // acco[i]: row ti+i, d-cols (tj2, tj2+1)
#pragma unroll 4
        for (int j = 0; j < 64; j++) {
            float4 p4 = *(const float4*)&xw[j][ti];
            ull xv = *(const ull*)&xs[j * 68 + tj2];
            fma2(acco[0], pk2(p4.x, p4.x), xv);
            fma2(acco[1], pk2(p4.y, p4.y), xv);
            fma2(acco[2], pk2(p4.z, p4.z), xv);
            fma2(acco[3], pk2(p4.w, p4.w), xv);
        }
        int d = d0 + tj2;
#pragma unroll
        for (int i = 0; i < 4; i++) {
            int row = ti + i;
            float o0, o1;
            upk2(acco[i], o0, o1);
            if (last) {
                if (d < DM)     dout[((size_t)batch * 64 + row) * DM + d]     = o0;
                if (d + 1 < DM) dout[((size_t)batch * 64 + row) * DM + d + 1] = o1;
            } else {
                float2 xv = *(const float2*)&xs[row * 68 + tj2];
                if (d < DM)     X[row * DM + d]     = o0 + xv.x;
                if (d + 1 < DM) X[row * DM + d + 1] = o1 + xv.y;
            }
        }
        __syncthreads();
    }
}

// ---------------------------------------------------------------------------
extern "C" void kernel_launch(void* const* d_in, const int* in_sizes, int n_in,
                              void* d_out, int out_size) {
    const int*   q1     = (const int*)d_in[0];
    const int*   q2     = (const int*)d_in[1];
    const int*   q1_len = (const int*)d_in[2];
    const int*   q2_len = (const int*)d_in[3];
    const int*   q1c    = (const int*)d_in[4];
    const int*   q2c    = (const int*)d_in[5];
    const float* wemb   = (const float*)d_in[6];
    const float* cemb   = (const float*)d_in[7];
    const float* cw3    = (const float*)d_in[8];
    const float* cb3    = (const float*)d_in[9];
    const float* cw4    = (const float*)d_in[10];
    const float* cb4    = (const float*)d_in[11];
    const float* cw5    = (const float*)d_in[12];
    const float* cb5    = (const float*)d_in[13];
    const float* hw_w   = (const float*)d_in[14];
    const float* hw_b   = (const float*)d_in[15];
    const float* attw   = (const float*)d_in[16];
    const float* attb   = (const float*)d_in[17];
    float* out = (float*)d_out;

    precomp_kernel<<<(60000 + 255) / 256, 256>>>(cemb, cw3, cw4, cw5);
    embed_kernel<<<NTOK, 160>>>(q1, q2, q1c, q2c, wemb, cb3, cb4, cb5);
    highway_kernel<<<dim3(8, 64), 512>>>(0, hw_w, hw_b);   // g_x -> g_y
    highway_kernel<<<dim3(8, 64), 512>>>(1, hw_w, hw_b);   // g_y -> g_x
    attn_kernel<<<128, 512>>>(q1_len, q2_len, attw, attb, 0, 0, out);
    attn_kernel<<<128, 512>>>(q1_len, q2_len, attw, attb, 1, 1, out);
}